// round 10
// baseline (speedup 1.0000x reference)
#include <cuda_runtime.h>
#include <math.h>

#define N2 512
#define DM 256
#define NSPLIT 8
#define KS 32        // k-width per split chunk
#define NBLK 512

__device__ float g_gram[NSPLIT][N2 * N2];   // partial Gram sums
__device__ float g_norm[N2];
__device__ float g_ts[N2];
__device__ int   g_perm[N2];
__device__ float g_part[N2];
__device__ volatile unsigned g_sense  = 0;  // barrier 1 release flag
__device__ unsigned g_count  = 0;           // barrier 1 arrivals
__device__ unsigned g_count2 = 0;           // barrier 2 arrivals

union SmemU {
    struct { float At[KS][68]; float Bt[KS][68]; } gemm;                      // 17408 B
    struct { float drow[N2], ts[N2], sv[N2], ds[N2], ps[N2], ss[N2]; } loss;  // 12288 B
};

__global__ void __launch_bounds__(256, 4) fused_kernel(
    const float* __restrict__ E, const float* __restrict__ T,
    float* __restrict__ out)
{
    __shared__ SmemU sm;
    __shared__ float wtot[8];
    __shared__ float red[8];
    __shared__ int   ri_sh;

    const int bid  = blockIdx.x;
    const int tid  = threadIdx.x;
    const int lane = tid & 31;
    const int w    = tid >> 5;

    // ======================= PHASE A: full-grid split-k Gram =======================
    // 64 tiles (8x8 of 64x64) x 8 k-splits = 512 chunks, exactly one per block.
    {
        const int tile  = bid >> 3;
        const int split = bid & 7;
        const int a = tile >> 3, b = tile & 7;
        const int kbase = split * KS;

        const int r  = tid >> 2;     // 0..63
        const int cq = tid & 3;      // 0..3
        const float* Ea = E + (a * 64 + r) * DM + kbase;
        const float* Eb = E + (b * 64 + r) * DM + kbase;

        float4 a1 = *reinterpret_cast<const float4*>(Ea + cq * 4);
        float4 a2 = *reinterpret_cast<const float4*>(Ea + 16 + cq * 4);
        float4 b1 = *reinterpret_cast<const float4*>(Eb + cq * 4);
        float4 b2 = *reinterpret_cast<const float4*>(Eb + 16 + cq * 4);

#define STORE_A(k, val) sm.gemm.At[(k)][(r + 8 * ((k) >> 3)) & 63] = (val)
#define STORE_B(k, val) sm.gemm.Bt[(k)][(r + 8 * ((k) >> 3)) & 63] = (val)
        {
            const int k1 = cq * 4, k2 = 16 + cq * 4;
            STORE_A(k1 + 0, a1.x); STORE_A(k1 + 1, a1.y);
            STORE_A(k1 + 2, a1.z); STORE_A(k1 + 3, a1.w);
            STORE_A(k2 + 0, a2.x); STORE_A(k2 + 1, a2.y);
            STORE_A(k2 + 2, a2.z); STORE_A(k2 + 3, a2.w);
            STORE_B(k1 + 0, b1.x); STORE_B(k1 + 1, b1.y);
            STORE_B(k1 + 2, b1.z); STORE_B(k1 + 3, b1.w);
            STORE_B(k2 + 0, b2.x); STORE_B(k2 + 1, b2.y);
            STORE_B(k2 + 2, b2.z); STORE_B(k2 + 3, b2.w);
        }
        __syncthreads();

        const int tx = tid & 15, ty = tid >> 4;
        const int ty4 = ty * 4, tx4 = tx * 4;

        float acc[4][4];
        #pragma unroll
        for (int x = 0; x < 4; x++)
            #pragma unroll
            for (int y = 0; y < 4; y++) acc[x][y] = 0.0f;

        #pragma unroll
        for (int kk = 0; kk < KS; kk++) {
            const int rot = 8 * (kk >> 3);
            float4 av = *reinterpret_cast<const float4*>(&sm.gemm.At[kk][(ty4 + rot) & 63]);
            float4 bv = *reinterpret_cast<const float4*>(&sm.gemm.Bt[kk][(tx4 + rot) & 63]);
            acc[0][0] = fmaf(av.x, bv.x, acc[0][0]);
            acc[0][1] = fmaf(av.x, bv.y, acc[0][1]);
            acc[0][2] = fmaf(av.x, bv.z, acc[0][2]);
            acc[0][3] = fmaf(av.x, bv.w, acc[0][3]);
            acc[1][0] = fmaf(av.y, bv.x, acc[1][0]);
            acc[1][1] = fmaf(av.y, bv.y, acc[1][1]);
            acc[1][2] = fmaf(av.y, bv.z, acc[1][2]);
            acc[1][3] = fmaf(av.y, bv.w, acc[1][3]);
            acc[2][0] = fmaf(av.z, bv.x, acc[2][0]);
            acc[2][1] = fmaf(av.z, bv.y, acc[2][1]);
            acc[2][2] = fmaf(av.z, bv.z, acc[2][2]);
            acc[2][3] = fmaf(av.z, bv.w, acc[2][3]);
            acc[3][0] = fmaf(av.w, bv.x, acc[3][0]);
            acc[3][1] = fmaf(av.w, bv.y, acc[3][1]);
            acc[3][2] = fmaf(av.w, bv.z, acc[3][2]);
            acc[3][3] = fmaf(av.w, bv.w, acc[3][3]);
        }

        float* G = g_gram[split];
        const int gi = a * 64 + ty4, gj = b * 64 + tx4;
        #pragma unroll
        for (int x = 0; x < 4; x++) {
            float4 o;
            o.x = acc[x][0]; o.y = acc[x][1]; o.z = acc[x][2]; o.w = acc[x][3];
            *reinterpret_cast<float4*>(&G[(gi + x) * N2 + gj]) = o;
        }
    }

    // ---- ranks + norms on blocks 448..511 (warp per element) ----
    if (bid >= 448) {
        const int e = (bid - 448) * 8 + w;
        const float tv = __ldg(&T[e]);
        int cnt = 0;
        #pragma unroll
        for (int c = 0; c < 16; c++) {
            int jj = lane + c * 32;
            float o = __ldg(&T[jj]);
            cnt += (o < tv || (o == tv && jj < e)) ? 1 : 0;
        }
        float nrm = 0.0f;
        #pragma unroll
        for (int c = 0; c < 8; c++) {
            float v = __ldg(&E[e * DM + lane + c * 32]);
            nrm = fmaf(v, v, nrm);
        }
        #pragma unroll
        for (int o = 16; o > 0; o >>= 1) {
            cnt += __shfl_xor_sync(0xffffffffu, cnt, o);
            nrm += __shfl_xor_sync(0xffffffffu, nrm, o);
        }
        if (lane == 0) { g_ts[cnt] = tv; g_perm[cnt] = e; g_norm[e] = nrm; }
    }

    // ======================= BARRIER 1 (volatile-load spin) =======================
    __syncthreads();
    if (tid == 0) {
        __threadfence();
        unsigned a = atomicAdd(&g_count, 1u);
        if (a == NBLK - 1) {
            g_count = 0;
            __threadfence();
            g_sense = 1u;           // release (plain volatile store)
        } else {
            while (g_sense != 1u) { __nanosleep(128); }
        }
        __threadfence();
    }
    __syncthreads();

    // ======================= PHASE B: loss row i = bid =======================
    {
        const int i = bid;
        const float ni = __ldg(&g_norm[i]);

        {
            float2 gsum = make_float2(0.0f, 0.0f);
            #pragma unroll
            for (int s = 0; s < NSPLIT; s++) {
                float2 gv = *reinterpret_cast<const float2*>(&g_gram[s][i * N2 + 2 * tid]);
                gsum.x += gv.x; gsum.y += gv.y;
            }
            float2 nv = *reinterpret_cast<const float2*>(&g_norm[2 * tid]);
            sm.loss.drow[2 * tid]     = sqrtf(fmaxf(ni + nv.x - 2.0f * gsum.x, 0.0f));
            sm.loss.drow[2 * tid + 1] = sqrtf(fmaxf(ni + nv.y - 2.0f * gsum.y, 0.0f));
            sm.loss.ts[2 * tid]     = g_ts[2 * tid];
            sm.loss.ts[2 * tid + 1] = g_ts[2 * tid + 1];
        }
        __syncthreads();

        const float ti = __ldg(&T[i]);

        #pragma unroll
        for (int c = 0; c < 2; c++) {
            int e = tid + c * 256;
            int p = g_perm[e];
            float d = sm.loss.drow[p];
            sm.loss.ds[e] = d;
            if (p == i) { sm.loss.sv[e] = 1.0f; ri_sh = e; }
            else        { sm.loss.sv[e] = __expf(-d); }
        }
        __syncthreads();

        // dual scan, additions only (thread owns sorted elements 2t, 2t+1)
        const float v0 = sm.loss.sv[2 * tid], v1 = sm.loss.sv[2 * tid + 1];
        const float pairv = v0 + v1;

        float p = pairv;
        #pragma unroll
        for (int off = 1; off < 32; off <<= 1) {
            float tmp = __shfl_up_sync(0xffffffffu, p, off);
            if (lane >= off) p += tmp;
        }
        float q = pairv;
        #pragma unroll
        for (int off = 1; off < 32; off <<= 1) {
            float tmp = __shfl_down_sync(0xffffffffu, q, off);
            if (lane + off < 32) q += tmp;
        }
        float pex = __shfl_up_sync(0xffffffffu, p, 1);
        if (lane == 0) pex = 0.0f;
        float sex = __shfl_down_sync(0xffffffffu, q, 1);
        if (lane == 31) sex = 0.0f;
        if (lane == 31) wtot[w] = p;
        __syncthreads();

        float offp = 0.0f, offs = 0.0f, total = 0.0f;
        #pragma unroll
        for (int ww = 0; ww < 8; ww++) {
            float tw = wtot[ww];
            total += tw;
            if (ww < w) offp += tw;
            if (ww > w) offs += tw;
        }
        const float bp = offp + pex;
        const float bs = offs + sex;
        sm.loss.ps[2 * tid]     = bp + v0;
        sm.loss.ps[2 * tid + 1] = bp + v0 + v1;
        sm.loss.ss[2 * tid + 1] = bs + v1;
        sm.loss.ss[2 * tid]     = bs + v1 + v0;
        __syncthreads();

        const int ri = ri_sh;
        const float* ts = sm.loss.ts;
        const float* ps = sm.loss.ps;
        const float* ss = sm.loss.ss;

        float local = 0.0f;
        #pragma unroll
        for (int c = 0; c < 2; c++) {
            int r = tid + c * 256;
            if (r == ri) continue;
            float denom;
            if (r > ri) {
                const float ak = ts[r] - ti;
                if (ak == 0.0f) {
                    denom = total - 1.0f;
                } else {
                    int R = r;
                    while (R > ri + 1 && (ts[R - 1] - ti >= ak)) R--;
                    int lo2 = 0, hi2 = ri;
                    while (lo2 < hi2) {
                        int m = (lo2 + hi2) >> 1;
                        if (ti - ts[m] >= ak) lo2 = m + 1; else hi2 = m;
                    }
                    const float dl = (lo2 > 0) ? ps[lo2 - 1] : 0.0f;
                    denom = dl + ss[R];
                }
            } else {
                const float ak = ti - ts[r];
                if (ak == 0.0f) {
                    denom = total - 1.0f;
                } else {
                    int lo = r + 1;
                    while (lo <= ri && (ti - ts[lo] >= ak)) lo++;
                    const float dl = ps[lo - 1];
                    int lo2 = ri + 1, hi2 = N2;
                    while (lo2 < hi2) {
                        int m = (lo2 + hi2) >> 1;
                        if (ts[m] - ti >= ak) hi2 = m; else lo2 = m + 1;
                    }
                    const float dr = (lo2 < N2) ? ss[lo2] : 0.0f;
                    denom = dl + dr;
                }
            }
            local += sm.loss.ds[r] + __logf(denom);
        }

        #pragma unroll
        for (int o = 16; o > 0; o >>= 1)
            local += __shfl_xor_sync(0xffffffffu, local, o);
        if (lane == 0) red[w] = local;
        __syncthreads();
        if (tid == 0) {
            float sum = 0.0f;
            #pragma unroll
            for (int k = 0; k < 8; k++) sum += red[k];
            g_part[bid] = sum;
        }
    }

    // ======================= BARRIER 2 (arrival-only) + PHASE C =======================
    __syncthreads();
    if (tid == 0) {
        __threadfence();
        atomicAdd(&g_count2, 1u);
    }
    if (bid != 0) return;

    if (tid == 0) {
        while (*((volatile unsigned*)&g_count2) != NBLK) { __nanosleep(128); }
        g_count2 = 0;   // reset for next graph replay
        g_sense  = 0;   // reset barrier-1 sense
        __threadfence();
    }
    __syncthreads();

    {
        float v = g_part[tid] + g_part[tid + 256];
        #pragma unroll
        for (int o = 16; o > 0; o >>= 1)
            v += __shfl_xor_sync(0xffffffffu, v, o);
        if (lane == 0) red[w] = v;
        __syncthreads();
        if (tid == 0) {
            float sum = 0.0f;
            #pragma unroll
            for (int k = 0; k < 8; k++) sum += red[k];
            const float scale = 1.0f / (float(N2) * float(N2 - 1));
            *out = sum * scale;
        }
    }
}

extern "C" void kernel_launch(void* const* d_in, const int* in_sizes, int n_in,
                              void* d_out, int out_size) {
    const float* E = (const float*)d_in[0];   // embeddings [512,256]
    const float* T = (const float*)d_in[1];   // targets    [512]
    float* out = (float*)d_out;

    fused_kernel<<<NBLK, 256>>>(E, T, out);
}

// round 12
// speedup vs baseline: 1.0135x; 1.0135x over previous
#include <cuda_runtime.h>
#include <math.h>

#define N2 512
#define DM 256
#define NSPLIT 16
#define KS 16        // k-width per split chunk
#define NBLK 512

__device__ float g_gram[NSPLIT][N2 * N2];   // partial Gram sums (16 MB)
__device__ float g_norm[N2];
__device__ float g_ts[N2];
__device__ int   g_perm[N2];
__device__ float g_part[N2];
__device__ volatile unsigned g_sense  = 0;  // barrier 1 release flag
__device__ unsigned g_count  = 0;           // barrier 1 arrivals
__device__ unsigned g_count2 = 0;           // barrier 2 arrivals

union SmemU {
    struct { float At[KS][136]; float Bt[KS][68]; } gemm;   // 8704 + 4352 = 13056 B
    struct { float drow[N2], ts[N2], ds[N2], sv[N2];
             float psX[N2 + 1], ssX[N2 + 1]; } loss;        // 12296 B
};

__global__ void __launch_bounds__(256, 4) fused_kernel(
    const float* __restrict__ E, const float* __restrict__ T,
    float* __restrict__ out)
{
    __shared__ SmemU sm;
    __shared__ float wtot[8];
    __shared__ float red[8];
    __shared__ int   ri_sh;

    const int bid  = blockIdx.x;
    const int tid  = threadIdx.x;
    const int lane = tid & 31;
    const int w    = tid >> 5;

    // ============ PHASE A: 128x64-tile split-k Gram, 8x4 microtile ============
    // bid -> (rt 0..3, ct 0..7, split 0..15): 4*8*16 = 512 chunks, 1 per block.
    {
        const int rt    = bid >> 7;
        const int ct    = (bid >> 4) & 7;
        const int split = bid & 15;
        const int kbase = split * KS;

        // load A tile: 128 rows x 16 k (2 float4 per thread)
        {
            const int r = tid >> 1, h = tid & 1;
            const float* Ep = E + (rt * 128 + r) * DM + kbase + h * 8;
            float4 v1 = *reinterpret_cast<const float4*>(Ep);
            float4 v2 = *reinterpret_cast<const float4*>(Ep + 4);
            const int kb = h * 8;
            sm.gemm.At[kb + 0][r] = v1.x; sm.gemm.At[kb + 1][r] = v1.y;
            sm.gemm.At[kb + 2][r] = v1.z; sm.gemm.At[kb + 3][r] = v1.w;
            sm.gemm.At[kb + 4][r] = v2.x; sm.gemm.At[kb + 5][r] = v2.y;
            sm.gemm.At[kb + 6][r] = v2.z; sm.gemm.At[kb + 7][r] = v2.w;
        }
        // load B tile: 64 rows x 16 k (1 float4 per thread)
        {
            const int j = tid >> 2, q = tid & 3;
            const float* Ep = E + (ct * 64 + j) * DM + kbase + q * 4;
            float4 v = *reinterpret_cast<const float4*>(Ep);
            const int kb = q * 4;
            sm.gemm.Bt[kb + 0][j] = v.x; sm.gemm.Bt[kb + 1][j] = v.y;
            sm.gemm.Bt[kb + 2][j] = v.z; sm.gemm.Bt[kb + 3][j] = v.w;
        }
        __syncthreads();

        const int tx = tid & 15, ty = tid >> 4;
        const int ty8 = ty * 8, tx4 = tx * 4;

        float acc[8][4];
        #pragma unroll
        for (int x = 0; x < 8; x++)
            #pragma unroll
            for (int y = 0; y < 4; y++) acc[x][y] = 0.0f;

        #pragma unroll
        for (int kk = 0; kk < KS; kk++) {
            float4 a0 = *reinterpret_cast<const float4*>(&sm.gemm.At[kk][ty8]);
            float4 a1 = *reinterpret_cast<const float4*>(&sm.gemm.At[kk][ty8 + 4]);
            float4 bv = *reinterpret_cast<const float4*>(&sm.gemm.Bt[kk][tx4]);
            float ax[8] = {a0.x, a0.y, a0.z, a0.w, a1.x, a1.y, a1.z, a1.w};
            #pragma unroll
            for (int x = 0; x < 8; x++) {
                acc[x][0] = fmaf(ax[x], bv.x, acc[x][0]);
                acc[x][1] = fmaf(ax[x], bv.y, acc[x][1]);
                acc[x][2] = fmaf(ax[x], bv.z, acc[x][2]);
                acc[x][3] = fmaf(ax[x], bv.w, acc[x][3]);
            }
        }

        float* G = g_gram[split];
        const int gi = rt * 128 + ty8, gj = ct * 64 + tx4;
        #pragma unroll
        for (int x = 0; x < 8; x++) {
            float4 o;
            o.x = acc[x][0]; o.y = acc[x][1]; o.z = acc[x][2]; o.w = acc[x][3];
            *reinterpret_cast<float4*>(&G[(gi + x) * N2 + gj]) = o;
        }
    }

    // ---- rank + norm for element bid (warp 0 of every block: uniform) ----
    if (w == 0) {
        const int e = bid;
        const float tv = __ldg(&T[e]);
        int cnt = 0;
        float nrm = 0.0f;
        #pragma unroll
        for (int c = 0; c < 16; c++) {
            int jj = lane + c * 32;
            float o = __ldg(&T[jj]);
            cnt += (o < tv || (o == tv && jj < e)) ? 1 : 0;
            if (c < 8) {
                float v = __ldg(&E[e * DM + jj]);
                nrm = fmaf(v, v, nrm);
            }
        }
        #pragma unroll
        for (int o = 16; o > 0; o >>= 1) {
            cnt += __shfl_xor_sync(0xffffffffu, cnt, o);
            nrm += __shfl_xor_sync(0xffffffffu, nrm, o);
        }
        if (lane == 0) { g_ts[cnt] = tv; g_perm[cnt] = e; g_norm[e] = nrm; }
    }

    // ============ BARRIER 1 (volatile-load spin) ============
    __syncthreads();
    if (tid == 0) {
        __threadfence();
        unsigned a = atomicAdd(&g_count, 1u);
        if (a == NBLK - 1) {
            g_count = 0;
            __threadfence();
            g_sense = 1u;
        } else {
            while (g_sense != 1u) { __nanosleep(64); }
        }
        __threadfence();
    }
    __syncthreads();

    // ============ PHASE B: loss row i = bid ============
    {
        const int i = bid;
        const float ni = __ldg(&g_norm[i]);

        {
            float2 gsum = make_float2(0.0f, 0.0f);
            #pragma unroll
            for (int s = 0; s < NSPLIT; s++) {
                float2 gv = *reinterpret_cast<const float2*>(&g_gram[s][i * N2 + 2 * tid]);
                gsum.x += gv.x; gsum.y += gv.y;
            }
            float2 nv = *reinterpret_cast<const float2*>(&g_norm[2 * tid]);
            sm.loss.drow[2 * tid]     = sqrtf(fmaxf(ni + nv.x - 2.0f * gsum.x, 0.0f));
            sm.loss.drow[2 * tid + 1] = sqrtf(fmaxf(ni + nv.y - 2.0f * gsum.y, 0.0f));
            sm.loss.ts[2 * tid]     = g_ts[2 * tid];
            sm.loss.ts[2 * tid + 1] = g_ts[2 * tid + 1];
        }
        __syncthreads();

        const float ti = __ldg(&T[i]);

        #pragma unroll
        for (int c = 0; c < 2; c++) {
            int e = tid + c * 256;
            int p = g_perm[e];
            float d = sm.loss.drow[p];
            sm.loss.ds[e] = d;
            if (p == i) { sm.loss.sv[e] = 1.0f; ri_sh = e; }
            else        { sm.loss.sv[e] = __expf(-d); }
        }
        __syncthreads();

        // dual scan, additions only (thread owns sorted elements 2t, 2t+1)
        const float v0 = sm.loss.sv[2 * tid], v1 = sm.loss.sv[2 * tid + 1];
        const float pairv = v0 + v1;

        float p = pairv;
        #pragma unroll
        for (int off = 1; off < 32; off <<= 1) {
            float tmp = __shfl_up_sync(0xffffffffu, p, off);
            if (lane >= off) p += tmp;
        }
        float q = pairv;
        #pragma unroll
        for (int off = 1; off < 32; off <<= 1) {
            float tmp = __shfl_down_sync(0xffffffffu, q, off);
            if (lane + off < 32) q += tmp;
        }
        float pex = __shfl_up_sync(0xffffffffu, p, 1);
        if (lane == 0) pex = 0.0f;
        float sex = __shfl_down_sync(0xffffffffu, q, 1);
        if (lane == 31) sex = 0.0f;
        if (lane == 31) wtot[w] = p;
        __syncthreads();

        float offp = 0.0f, offs = 0.0f, total = 0.0f;
        #pragma unroll
        for (int ww = 0; ww < 8; ww++) {
            float tw = wtot[ww];
            total += tw;
            if (ww < w) offp += tw;
            if (ww > w) offs += tw;
        }
        const float bp = offp + pex;
        const float bs = offs + sex;
        // psX[m] = sum of first m sorted s-values (psX[0]=0); ssX[m] = suffix from m (ssX[512]=0)
        sm.loss.psX[2 * tid + 1] = bp + v0;
        sm.loss.psX[2 * tid + 2] = bp + v0 + v1;
        sm.loss.ssX[2 * tid]     = bs + v1 + v0;
        sm.loss.ssX[2 * tid + 1] = bs + v1;
        if (tid == 0) { sm.loss.psX[0] = 0.0f; sm.loss.ssX[N2] = 0.0f; }
        __syncthreads();

        const int ri = ri_sh;
        const float* ts  = sm.loss.ts;
        const float* psX = sm.loss.psX;
        const float* ssX = sm.loss.ssX;

        // uniform branchless denom: L = #{m: ti-ts[m] >= ak}, R = first{m: ts[m]-ti >= ak}
        // denom = psX[L] + ssX[R]  (disjoint prefix+suffix for ak>0; self auto-excluded)
        const int r1 = tid, r2 = tid + 256;
        const float ak1 = fabsf(ti - ts[r1]);
        const float ak2 = fabsf(ti - ts[r2]);
        int L1 = 0, L2 = 0, R1 = 0, R2 = 0;
        #pragma unroll
        for (int step = 256; step > 0; step >>= 1) {
            if (ti - ts[L1 + step - 1] >= ak1) L1 += step;
            if (ti - ts[L2 + step - 1] >= ak2) L2 += step;
            if (ts[R1 + step - 1] - ti <  ak1) R1 += step;
            if (ts[R2 + step - 1] - ti <  ak2) R2 += step;
        }
        // R can legitimately be 512 (no right-side element qualifies); steps sum
        // to 511, so apply one extra probe (in-bounds: R <= 511 here). L <= 511
        // is guaranteed (self fails its own predicate), no fixup needed.
        if (ts[R1] - ti < ak1) R1++;
        if (ts[R2] - ti < ak2) R2++;
        float den1 = psX[L1] + ssX[R1];
        float den2 = psX[L2] + ssX[R2];
        if (ak1 == 0.0f) den1 = total - 1.0f;
        if (ak2 == 0.0f) den2 = total - 1.0f;
        float local = 0.0f;
        if (r1 != ri) local += sm.loss.ds[r1] + __logf(den1);
        if (r2 != ri) local += sm.loss.ds[r2] + __logf(den2);

        #pragma unroll
        for (int o = 16; o > 0; o >>= 1)
            local += __shfl_xor_sync(0xffffffffu, local, o);
        if (lane == 0) red[w] = local;
        __syncthreads();
        if (tid == 0) {
            float sum = 0.0f;
            #pragma unroll
            for (int k = 0; k < 8; k++) sum += red[k];
            g_part[bid] = sum;
        }
    }

    // ============ BARRIER 2 (arrival-only) + PHASE C ============
    __syncthreads();
    if (tid == 0) {
        __threadfence();
        atomicAdd(&g_count2, 1u);
    }
    if (bid != 0) return;

    if (tid == 0) {
        while (*((volatile unsigned*)&g_count2) != NBLK) { __nanosleep(64); }
        g_count2 = 0;   // reset for next graph replay
        g_sense  = 0;   // reset barrier-1 sense
        __threadfence();
    }
    __syncthreads();

    {
        float v = g_part[tid] + g_part[tid + 256];
        #pragma unroll
        for (int o = 16; o > 0; o >>= 1)
            v += __shfl_xor_sync(0xffffffffu, v, o);
        if (lane == 0) red[w] = v;
        __syncthreads();
        if (tid == 0) {
            float sum = 0.0f;
            #pragma unroll
            for (int k = 0; k < 8; k++) sum += red[k];
            const float scale = 1.0f / (float(N2) * float(N2 - 1));
            *out = sum * scale;
        }
    }
}

extern "C" void kernel_launch(void* const* d_in, const int* in_sizes, int n_in,
                              void* d_out, int out_size) {
    const float* E = (const float*)d_in[0];   // embeddings [512,256]
    const float* T = (const float*)d_in[1];   // targets    [512]
    float* out = (float*)d_out;

    fused_kernel<<<NBLK, 256>>>(E, T, out);
}